// round 9
// baseline (speedup 1.0000x reference)
#include <cuda_runtime.h>
#include <cuda_fp16.h>
#include <cstdint>

#define BB 4
#define NN 256
#define HH 8

// ---------------- scratch ----------------
__device__ float g_WT[256 * 256];
__device__ float g_WodT[256 * 256];
__device__ float g_Wh[BB * NN * 256];
__device__ float g_od[BB * NN * 256];
__device__ float g_Whi[BB * NN * HH];
__device__ float g_Whj[BB * NN * HH];
__device__ float g_e[BB * HH * NN * NN];   // exp(leaky(logit)) (masked -> 0)

__device__ __forceinline__ uint32_t smem_u32(const void* p) {
    uint32_t a;
    asm("{ .reg .u64 t; cvta.to.shared.u64 t, %1; cvt.u32.u64 %0, t; }"
        : "=r"(a) : "l"(p));
    return a;
}
__device__ __forceinline__ uint32_t pkh2(float lo, float hi) {
    __half2 h = __floats2half2_rn(lo, hi);
    return *reinterpret_cast<uint32_t*>(&h);
}
__device__ __forceinline__ void mma16(float* c, uint32_t a0, uint32_t a1,
                                      uint32_t a2, uint32_t a3,
                                      uint32_t b0, uint32_t b1) {
    asm volatile(
        "mma.sync.aligned.m16n8k16.row.col.f32.f16.f16.f32 "
        "{%0,%1,%2,%3},{%4,%5,%6,%7},{%8,%9},{%0,%1,%2,%3};"
        : "+f"(c[0]), "+f"(c[1]), "+f"(c[2]), "+f"(c[3])
        : "r"(a0), "r"(a1), "r"(a2), "r"(a3), "r"(b0), "r"(b1));
}
#define LDSM4(r0, r1, r2, r3, addr) \
    asm volatile("ldmatrix.sync.aligned.m8n8.x4.shared.b16 {%0,%1,%2,%3},[%4];" \
                 : "=r"(r0), "=r"(r1), "=r"(r2), "=r"(r3) : "r"(addr))

// ---------------- K0: transpose weights for k_node ----------------
__global__ __launch_bounds__(256) void k_transpose(
    const float* __restrict__ W_w, const float* __restrict__ Wod_w)
{
    int i = blockIdx.x * blockDim.x + threadIdx.x;
    int stride = gridDim.x * blockDim.x;
    for (int idx = i; idx < 65536; idx += stride) {
        int c = idx >> 8, t = idx & 255;
        g_WT[idx] = W_w[t * 256 + c];
        g_WodT[idx] = Wod_w[t * 256 + c];
    }
}

// ---------------- K1: Wh, od, Whi, Whj ----------------
__global__ __launch_bounds__(256) void k_node(
    const float* __restrict__ node_fea,
    const float* __restrict__ W_b, const float* __restrict__ Wod_b,
    const float* __restrict__ a1_w, const float* __restrict__ a2_w)
{
    __shared__ float nf_s[8][256];
    __shared__ float wh_s[8][256];
    int t = threadIdx.x;
    int b = blockIdx.y;
    int i0 = blockIdx.x * 8;

    for (int x = t; x < 8 * 256; x += 256) {
        int r = x >> 8, c = x & 255;
        int h = c >> 5, d = c & 31;
        nf_s[r][c] = node_fea[((b * HH + h) * NN + (i0 + r)) * 32 + d];
    }
    __syncthreads();

    float wh[8], odv[8];
    float wb = W_b[t], wob = Wod_b[t];
#pragma unroll
    for (int r = 0; r < 8; ++r) { wh[r] = wb; odv[r] = wob; }

#pragma unroll 4
    for (int c = 0; c < 256; ++c) {
        float wt = g_WT[c * 256 + t];
        float wo = g_WodT[c * 256 + t];
#pragma unroll
        for (int r = 0; r < 8; ++r) {
            float nv = nf_s[r][c];
            wh[r] = fmaf(nv, wt, wh[r]);
            odv[r] = fmaf(nv, wo, odv[r]);
        }
    }
#pragma unroll
    for (int r = 0; r < 8; ++r) {
        int row = b * NN + i0 + r;
        g_Wh[row * 256 + t] = wh[r];
        g_od[row * 256 + t] = odv[r];
        wh_s[r][t] = wh[r];
    }
    __syncthreads();

    int wid = t >> 5, lane = t & 31;
#pragma unroll 1
    for (int r = 0; r < 8; ++r) {
        float s1 = 0.f, s2 = 0.f;
#pragma unroll
        for (int k = 0; k < 8; ++k) {
            int c = lane + k * 32;
            float wv = wh_s[r][c];
            s1 = fmaf(wv, a1_w[wid * 256 + c], s1);
            s2 = fmaf(wv, a2_w[wid * 256 + c], s2);
        }
#pragma unroll
        for (int off = 16; off; off >>= 1) {
            s1 += __shfl_down_sync(0xffffffffu, s1, off);
            s2 += __shfl_down_sync(0xffffffffu, s2, off);
        }
        if (lane == 0) {
            int row = b * NN + i0 + r;
            g_Whi[row * 8 + wid] = s1;
            g_Whj[row * 8 + wid] = s2;
        }
    }
}

// ---------------- K2: fp16 mma edge kernel, i-locality + smem od tile ----------
// tile v: ii = v&7, unit = v>>3; ig=unit&31, j0i=(unit>>5)&3, b=(unit>>7)&3,
//         nh=(unit>>9)&1;  i = ig*8+ii, j0 = j0i*64
// od tile (b,j0,nh) constant over 256 consecutive v -> smem-cached.
// smem: sB4 32KB @0 | sB8 2KB @32768 | sA16 17KB @34816 |
//       s_od 64*144*4 @52224 | s_oib 512B @89088
#define OFF_B4 0
#define OFF_B8 32768
#define OFF_A16 34816
#define OFF_OD 52224
#define OFF_OIB 89088
#define EDGE_SMEM 89600
#define NTILES 8192
#define EGRID 296

__global__ __launch_bounds__(256, 2) void k_edge_mma(
    const float* __restrict__ edge_fea, const int* __restrict__ adj,
    const float* __restrict__ ae_w, const float* __restrict__ ae_b,
    const float* __restrict__ We_w, const float* __restrict__ We_b,
    float* __restrict__ edge_out)
{
    extern __shared__ char smc[];
    uint4* sB4 = reinterpret_cast<uint4*>(smc + OFF_B4);
    uint2* sB8 = reinterpret_cast<uint2*>(smc + OFF_B8);
    char* sA16 = smc + OFF_A16;
    float* s_od = reinterpret_cast<float*>(smc + OFF_OD);    // [64][144]
    float* s_oib = reinterpret_cast<float*>(smc + OFF_OIB);  // [128]
    uint32_t sA_u = smem_u32(sA16);

    int t = threadIdx.x;
    int w = t >> 5, lane = t & 31;
    int mg = w >> 2, ng = w & 3;
    int lr = lane >> 2, lc = lane & 3;

    uint32_t lds_base = sA_u + (uint32_t)((mg * 32 + (lane & 15)) * 272 +
                                          (lane >> 4) * 16);

    // contiguous v-range per CTA: 8192 = 296*27 + 200
    int bx = blockIdx.x;
    int v0 = bx * 27 + (bx < 200 ? bx : 200);
    int v1 = v0 + 27 + (bx < 200 ? 1 : 0);

    int cur_nh = -1, cur_key = -1;

    for (int v = v0; v < v1; ++v) {
        int ii = v & 7, unit = v >> 3;
        int ig = unit & 31, j0i = (unit >> 5) & 3;
        int b = (unit >> 7) & 3, nh = (unit >> 9) & 1;
        int i = ig * 8 + ii, j0 = j0i << 6;
        int key = unit >> 5;       // (nh,b,j0)

        // ---- repack B on nh change (rare) ----
        if (nh != cur_nh) {
            for (int x = t; x < 2048; x += 256) {
                int s = x >> 8, np = (x >> 5) & 7, l = x & 31;
                int rn = l >> 2, plc = l & 3;
                int n0 = nh * 128 + np * 16 + ((rn >> 1) << 2) + (rn & 1);
                int k0 = s * 16 + plc * 2;
                const float* w0 = We_w + n0 * 128 + k0;
                const float* w1 = We_w + (n0 + 2) * 128 + k0;
                uint4 pk;
                pk.x = pkh2(w0[0], w0[1]);
                pk.y = pkh2(w0[8], w0[9]);
                pk.z = pkh2(w1[0], w1[1]);
                pk.w = pkh2(w1[8], w1[9]);
                sB4[x] = pk;
            }
            if (cur_nh < 0 && t < 256) {   // ae logit frags (once)
                int s = t >> 5, l = t & 31;
                int rn = l >> 2, plc = l & 3;
                const float* src = ae_w + rn * 128 + s * 16 + plc * 2;
                uint2 pk;
                pk.x = pkh2(src[0], src[1]);
                pk.y = pkh2(src[8], src[9]);
                sB8[t] = pk;
            }
            cur_nh = nh;
        }

        // ---- load od j-tile to smem on key change (once per ~256 tiles) ----
        if (key != cur_key) {
#pragma unroll
            for (int q = 0; q < 8; ++q) {
                int idx = q * 256 + t;
                int j = idx >> 5, nq = idx & 31;     // nq: float4 col 0..31
                float4 vv = *reinterpret_cast<const float4*>(
                    g_od + (b * NN + j0 + j) * 256 + nh * 128 + nq * 4);
                *reinterpret_cast<float4*>(s_od + j * 144 + nq * 4) = vv;
            }
            cur_key = key;
        }

        // ---- A load: 64j x 128k fp32 -> fp16 smem ----
#pragma unroll
        for (int it = 0; it < 8; ++it) {
            int idx = it * 256 + t;
            int h = idx >> 8, r = idx & 255, j = r >> 2, dq = r & 3;
            float4 vv = *reinterpret_cast<const float4*>(
                edge_fea + ((((b * 8 + h) * NN + i) * NN) + j0 + j) * 16 + dq * 4);
            uint2 pk;
            pk.x = pkh2(vv.x, vv.y);
            pk.y = pkh2(vv.z, vv.w);
            *reinterpret_cast<uint2*>(sA16 + j * 272 + h * 32 + dq * 8) = pk;
        }
        if (t < 128)
            s_oib[t] = g_od[(b * NN + i) * 256 + nh * 128 + t] +
                       We_b[nh * 128 + t];
        __syncthreads();

        // ---- mainloop ----
        float c[2][4][4];
        float c8[2][4];
#pragma unroll
        for (int a = 0; a < 2; ++a) {
#pragma unroll
            for (int n = 0; n < 4; ++n)
#pragma unroll
                for (int q = 0; q < 4; ++q) c[a][n][q] = 0.f;
#pragma unroll
            for (int q = 0; q < 4; ++q) c8[a][q] = 0.f;
        }

#pragma unroll
        for (int s = 0; s < 8; ++s) {
            uint32_t A[2][4];
#pragma unroll
            for (int m = 0; m < 2; ++m)
                LDSM4(A[m][0], A[m][1], A[m][2], A[m][3],
                      lds_base + (uint32_t)(m * 4352 + s * 32));
            uint4 Bv[2];
#pragma unroll
            for (int p = 0; p < 2; ++p)
                Bv[p] = sB4[(s * 8 + ng * 2 + p) * 32 + lane];
#pragma unroll
            for (int m = 0; m < 2; ++m)
#pragma unroll
                for (int p = 0; p < 2; ++p) {
                    mma16(c[m][2 * p], A[m][0], A[m][1], A[m][2], A[m][3],
                          Bv[p].x, Bv[p].y);
                    mma16(c[m][2 * p + 1], A[m][0], A[m][1], A[m][2], A[m][3],
                          Bv[p].z, Bv[p].w);
                }
            if (nh == 0 && ng == 0) {
                uint2 B8 = sB8[s * 32 + lane];
#pragma unroll
                for (int m = 0; m < 2; ++m)
                    mma16(c8[m], A[m][0], A[m][1], A[m][2], A[m][3],
                          B8.x, B8.y);
            }
        }

        // ---- logits epilogue (nh==0, ng==0): store exp(leaky), masked -> 0
        if (nh == 0 && ng == 0) {
            int hp = lc * 2;
            float2 whi = *reinterpret_cast<const float2*>(
                g_Whi + (b * NN + i) * 8 + hp);
            float2 aeb = *reinterpret_cast<const float2*>(ae_b + hp);
            float bi0 = whi.x + aeb.x, bi1 = whi.y + aeb.y;
            const int* adjrow = adj + (b * NN + i) * NN;
#pragma unroll
            for (int m = 0; m < 2; ++m) {
                int jg = j0 + mg * 32 + m * 16 + lr;
#pragma unroll
                for (int half = 0; half < 2; ++half) {
                    int row = jg + half * 8;
                    float2 whj = *reinterpret_cast<const float2*>(
                        g_Whj + (b * NN + row) * 8 + hp);
                    int av = adjrow[row];
                    float e0 = c8[m][half * 2] + bi0 + whj.x;
                    float e1 = c8[m][half * 2 + 1] + bi1 + whj.y;
                    e0 = (e0 > 0.f) ? e0 : 0.2f * e0;
                    e1 = (e1 > 0.f) ? e1 : 0.2f * e1;
                    float p0 = (av <= 0) ? 0.f : __expf(e0);
                    float p1 = (av <= 0) ? 0.f : __expf(e1);
                    g_e[((b * 8 + hp) * NN + i) * NN + row] = p0;
                    g_e[((b * 8 + hp + 1) * NN + i) * NN + row] = p1;
                }
            }
        }

        // ---- edge stores: od_j from smem tile ----
#pragma unroll
        for (int p = 0; p < 2; ++p) {
            int npg = nh * 8 + ng * 2 + p;
            int h = npg >> 1;
            int nloc = ((ng * 2 + p) << 4) + (lc << 2);
            int dd = (npg << 4 & 31) + (lc << 2);
            float4 ob = *reinterpret_cast<const float4*>(s_oib + nloc);
            int rowbase = ((b * 8 + h) * NN + i) * NN;
#pragma unroll
            for (int m = 0; m < 2; ++m) {
#pragma unroll
                for (int h2 = 0; h2 < 2; ++h2) {
                    int jj = mg * 32 + m * 16 + lr + h2 * 8;
                    float4 od = *reinterpret_cast<const float4*>(
                        s_od + jj * 144 + nloc);
                    float4 o;
                    o.x = c[m][2 * p][h2 * 2 + 0] + ob.x + od.x;
                    o.y = c[m][2 * p][h2 * 2 + 1] + ob.y + od.y;
                    o.z = c[m][2 * p + 1][h2 * 2 + 0] + ob.z + od.z;
                    o.w = c[m][2 * p + 1][h2 * 2 + 1] + ob.w + od.w;
                    *reinterpret_cast<float4*>(
                        edge_out + (size_t)(rowbase + j0 + jj) * 32 + dd) = o;
                }
            }
        }
        __syncthreads();   // sA16 / s_oib / s_od reuse next iteration
    }
}

// ---------------- K3: normalize pre-exp'd scores + node_new ----------------
__global__ __launch_bounds__(256) void k_attn3(float* __restrict__ node_out)
{
    extern __shared__ float sm2[];
    float* Whs = sm2;            // [256][32]
    float* att = sm2 + 8192;     // [16][256]
    int t = threadIdx.x, w = t >> 5, lane = t & 31;
    int i0 = blockIdx.x << 4, h = blockIdx.y, b = blockIdx.z;

    float4* Wh4 = reinterpret_cast<float4*>(Whs);
    const float4* g4 = reinterpret_cast<const float4*>(g_Wh);
    for (int x = t; x < 2048; x += 256) {
        int j = x >> 3, dq = x & 7;
        Wh4[x] = g4[(b * NN + j) * 64 + (h << 3) + dq];
    }

    const float4* e4 = reinterpret_cast<const float4*>(g_e);
    float4 xv[4];
#pragma unroll
    for (int r = 0; r < 2; ++r) {
        int i = i0 + w + (r << 3);
        int idx = (((b << 3) + h) * NN + i) * 64 + (lane << 1);
        xv[2 * r] = e4[idx];
        xv[2 * r + 1] = e4[idx + 1];
    }
    __syncthreads();

#pragma unroll
    for (int r = 0; r < 2; ++r) {
        int il = w + (r << 3);
        float4 x0 = xv[2 * r], x1 = xv[2 * r + 1];
        float s = ((x0.x + x0.y) + (x0.z + x0.w)) +
                  ((x1.x + x1.y) + (x1.z + x1.w));
#pragma unroll
        for (int o = 16; o; o >>= 1)
            s += __shfl_xor_sync(0xffffffffu, s, o);
        float rinv = 1.0f / s;
        float4 y0 = {x0.x * rinv, x0.y * rinv, x0.z * rinv, x0.w * rinv};
        float4 y1 = {x1.x * rinv, x1.y * rinv, x1.z * rinv, x1.w * rinv};
        float4* arow = reinterpret_cast<float4*>(att + il * 256);
        arow[lane * 2] = y0;
        arow[lane * 2 + 1] = y1;
    }
    __syncthreads();

    float acc0 = 0.f, acc1 = 0.f;
    const float4* a0 = reinterpret_cast<const float4*>(att + w * 256);
    const float4* a1 = reinterpret_cast<const float4*>(att + (w + 8) * 256);
#pragma unroll 4
    for (int jq = 0; jq < 64; ++jq) {
        int j = jq << 2;
        float w0 = Whs[j * 32 + lane];
        float w1 = Whs[(j + 1) * 32 + lane];
        float w2 = Whs[(j + 2) * 32 + lane];
        float w3 = Whs[(j + 3) * 32 + lane];
        float4 q;
        q = a0[jq]; acc0 += q.x * w0 + q.y * w1 + q.z * w2 + q.w * w3;
        q = a1[jq]; acc1 += q.x * w0 + q.y * w1 + q.z * w2 + q.w * w3;
    }
    {
        int i = i0 + w;
        node_out[(((b << 3) + h) * NN + i) * 32 + lane] =
            acc0 + Whs[i * 32 + lane];
        i = i0 + w + 8;
        node_out[(((b << 3) + h) * NN + i) * 32 + lane] =
            acc1 + Whs[i * 32 + lane];
    }
}

// ---------------- launch ----------------
extern "C" void kernel_launch(void* const* d_in, const int* in_sizes, int n_in,
                              void* d_out, int out_size)
{
    const float* node_fea = (const float*)d_in[0];
    const float* edge_fea = (const float*)d_in[1];
    const int* adj = (const int*)d_in[2];
    const float* W_w = (const float*)d_in[3];
    const float* W_b = (const float*)d_in[4];
    const float* a1_w = (const float*)d_in[5];
    const float* a2_w = (const float*)d_in[6];
    const float* ae_w = (const float*)d_in[7];
    const float* ae_b = (const float*)d_in[8];
    const float* We_w = (const float*)d_in[9];
    const float* We_b = (const float*)d_in[10];
    const float* Wod_w = (const float*)d_in[11];
    const float* Wod_b = (const float*)d_in[12];

    float* out = (float*)d_out;
    float* node_out = out;                       // [B,H,N,DNO]
    float* edge_out = out + BB * HH * NN * 32;   // [B,H,N,N,DEO]

    cudaFuncSetAttribute(k_edge_mma, cudaFuncAttributeMaxDynamicSharedMemorySize,
                         EDGE_SMEM);
    cudaFuncSetAttribute(k_attn3, cudaFuncAttributeMaxDynamicSharedMemorySize,
                         49152);

    k_transpose<<<128, 256>>>(W_w, Wod_w);
    k_node<<<dim3(32, BB), 256>>>(node_fea, W_b, Wod_b, a1_w, a2_w);
    k_edge_mma<<<EGRID, 256, EDGE_SMEM>>>(edge_fea, adj, ae_w, ae_b, We_w, We_b,
                                          edge_out);
    k_attn3<<<dim3(16, HH, BB), 256, 49152>>>(node_out);
}